// round 17
// baseline (speedup 1.0000x reference)
#include <cuda_runtime.h>
#include <math_constants.h>

#define CCH   512
#define HH    64
#define WW    64
#define FX    7
#define FY    7
#define BINS  (FX*FY)            // 49
#define SEG   (CCH*BINS)         // 25088
#define DTOT  (SEG*6)            // 150528
#define NOUT  1024
#define KCHUNK 256
#define NCHUNKS (DTOT/KCHUNK)    // 588
#define MAXSPAN 10               // max rows/cols per adaptive bin for 64-size dim
#define PGRP  4                  // pools per block (4 blocks per channel)
#define RPARTS 32                // reduce: K-part slices per block
#define RCPP  19                 // ceil(588/32) chunks per part

// Prefetch: first 160 KB of each 1 MB GEMM chunk -> 94 MB into L2
#define PF_LPC   1280                       // 128B lines per chunk (160 KB)
#define PF_TOTAL (NCHUNKS * PF_LPC)         // 752,640 lines
#define PF_BLKS  296
#define PF_THREADS (PF_BLKS * 256)          // 75,776
#define PF_ITERS 10                         // ceil(752640 / 75776)

// Scratch (no allocation allowed in kernel_launch)
__device__ float g_pools[16 * SEG];              // 16 pools, each [C, FX, FY] channel-major
__device__ float g_partial[NCHUNKS * 3 * NOUT];  // 7.2 MB

// ---------------------------------------------------------------------------
// Prefetch kernel: issues fire-and-forget L2 prefetches for the first 160 KB
// of every GEMM K-chunk of W (94 MB). No writeback, no dependencies -> the
// kernel retires in a few us while the L2 fills continue in the background,
// overlapping the entire pool kernel (L2 persists across launches).
// ---------------------------------------------------------------------------
__global__ void __launch_bounds__(256) prefetch_kernel(const float* __restrict__ Wf)
{
    int idx = blockIdx.x * 256 + threadIdx.x;
    #pragma unroll
    for (int k = 0; k < PF_ITERS; k++) {
        int l = idx + k * PF_THREADS;
        if (l < PF_TOTAL) {
            int c   = l / PF_LPC;
            int off = l - c * PF_LPC;
            const char* p = (const char*)Wf
                          + (size_t)c * (KCHUNK * NOUT * 4)
                          + (size_t)off * 128;
            asm volatile("prefetch.global.L2 [%0];" :: "l"(p));
        }
    }
}

// ---------------------------------------------------------------------------
// Pool kernel: grid (512 channels, 4 pool-groups), 256 threads. Separable
// 2-pass adaptive max; pass 1 reads the feature plane directly from global
// (coalesced float2, L1-resident); bounds precomputed to SMEM tables; hot
// loops fixed-trip (10) with index clamped to the bin's last valid element
// (idempotent re-max -> no predicates).
// Pool index map: 0 = scene, 1..3 = human[i], 4..15 = obj-union(i,j) (i*4+j).
// ---------------------------------------------------------------------------
__global__ void __launch_bounds__(256) pool_kernel(
    const float* __restrict__ feature,
    const float* __restrict__ pbox,   // [3,4] x1,y1,x2,y2 (image coords)
    const float* __restrict__ obox,   // [4,4]
    const float* __restrict__ ratio)  // [2]
{
    __shared__ float strip[PGRP * FX * WW];          // 7 KB  [pl*FX+i][x]
    __shared__ int by0[PGRP], by1[PGRP], bxx0[PGRP], bxx1[PGRP];
    __shared__ int srs[PGRP * FX], sre[PGRP * FX];   // row-bin bounds per (pl,i)
    __shared__ int scs[PGRP * FY], sce[PGRP * FY];   // col-bin bounds per (pl,j)

    const int ch    = blockIdx.x;
    const int pbase = blockIdx.y * PGRP;
    const int tid   = threadIdx.x;

    if (tid < PGRP) {
        const float rx = ratio[0], ry = ratio[1];
        int p = pbase + tid;
        int x0, y0, x1, y1;
        if (p == 0) {
            x0 = 0; y0 = 0; x1 = WW; y1 = HH;
        } else if (p < 4) {
            int i = p - 1;
            x0 = (int)rintf(pbox[i*4+0] * rx);
            y0 = (int)rintf(pbox[i*4+1] * ry);
            x1 = (int)rintf(pbox[i*4+2] * rx);
            y1 = (int)rintf(pbox[i*4+3] * ry);
        } else {
            int q = p - 4; int i = q >> 2; int j = q & 3;
            int px0 = (int)rintf(pbox[i*4+0] * rx);
            int py0 = (int)rintf(pbox[i*4+1] * ry);
            int px1 = (int)rintf(pbox[i*4+2] * rx);
            int py1 = (int)rintf(pbox[i*4+3] * ry);
            int ox0 = (int)rintf(obox[j*4+0] * rx);
            int oy0 = (int)rintf(obox[j*4+1] * ry);
            int ox1 = (int)rintf(obox[j*4+2] * rx);
            int oy1 = (int)rintf(obox[j*4+3] * ry);
            x0 = min(px0, ox0); y0 = min(py0, oy0);
            x1 = max(px1, ox1); y1 = max(py1, oy1);
        }
        bxx0[tid] = x0; by0[tid] = y0; bxx1[tid] = x1; by1[tid] = y1;
    }
    __syncthreads();

    // Bin-bound tables (divisions by 7 happen once, outside hot loops).
    if (tid < PGRP * FX) {
        int pl = tid / FX, i = tid - pl * FX;
        int y0 = by0[pl], h = by1[pl] - y0;
        srs[tid] = y0 + (i * h) / FX;
        sre[tid] = y0 + ((i + 1) * h + FX - 1) / FX;
    } else if (tid >= 64 && tid < 64 + PGRP * FY) {
        int t = tid - 64;
        int pl = t / FY, j = t - pl * FY;
        int x0 = bxx0[pl], w = bxx1[pl] - x0;
        scs[t] = x0 + (j * w) / FY;
        sce[t] = x0 + ((j + 1) * w + FY - 1) / FY;
    }
    __syncthreads();

    // Pass 1: 28 strips over 8 warps (<=4 serial strips/warp). Lane = column
    // pair; reads go straight to global (L1-resident after first touch).
    {
        const int warp = tid >> 5;
        const int lane = tid & 31;
        const float2* fp = (const float2*)(feature + (size_t)ch * (HH * WW));
        #pragma unroll
        for (int s = 0; s < 4; s++) {
            const int t = warp + s * 8;
            if (t < PGRP * FX) {
                const int rs = srs[t];
                const int rl = sre[t] - 1;      // last valid row of this bin
                float2 m = make_float2(-CUDART_INF_F, -CUDART_INF_F);
                #pragma unroll
                for (int k = 0; k < MAXSPAN; k++) {
                    int r = min(rs + k, rl);    // idempotent re-max when past end
                    float2 v = __ldg(fp + r * (WW / 2) + lane);
                    m.x = fmaxf(m.x, v.x);
                    m.y = fmaxf(m.y, v.y);
                }
                strip[t * WW + 2 * lane]     = m.x;
                strip[t * WW + 2 * lane + 1] = m.y;
            }
        }
    }
    __syncthreads();

    // Pass 2: 196 bins over 256 threads (1 each). Unroll 10, clamped-idempotent.
    if (tid < PGRP * BINS) {
        int pl  = tid / BINS;
        int bin = tid - pl * BINS;
        int i = bin / FY, j = bin - i * FY;
        int cs = scs[pl * FY + j];
        int cl = sce[pl * FY + j] - 1;          // last valid col of this bin
        const float* s = strip + (pl * FX + i) * WW;
        float m = -CUDART_INF_F;
        #pragma unroll
        for (int k = 0; k < MAXSPAN; k++) {
            int c = min(cs + k, cl);
            m = fmaxf(m, s[c]);
        }
        g_pools[(pbase + pl) * SEG + ch * BINS + bin] = m;
    }
}

// ---------------------------------------------------------------------------
// Split-K GEMM: out[m,n] = sum_d act[m,d] * W[d,n]
// act row m = concat(human[m], obj[4m..4m+3], scene); each 256-row K-chunk
// lies entirely in one concat segment (256 divides 25088), so activations
// are 3 base pointers into g_pools, staged in SMEM.
// One block = all 1024 N columns (256 thr x float4), one K-chunk of 256.
// The first 160 KB of each chunk was L2-prefetched by prefetch_kernel.
// ---------------------------------------------------------------------------
__global__ void __launch_bounds__(256, 4) gemm_kernel(const float* __restrict__ Wf)
{
    __shared__ float sa0[KCHUNK], sa1[KCHUNK], sa2[KCHUNK];

    const int chunk  = blockIdx.x;
    const int k0     = chunk * KCHUNK;
    const int seg    = k0 / SEG;            // 0..5
    const int within = k0 - seg * SEG;

    int p0, p1, p2;
    if (seg == 0)      { p0 = 1;       p1 = 2;       p2 = 3;       } // human[m]
    else if (seg == 5) { p0 = 0;       p1 = 0;       p2 = 0;       } // scene
    else               { p0 = 3 + seg; p1 = 7 + seg; p2 = 11 + seg; } // obj[4m+seg-1]

    const int tid = threadIdx.x;
    sa0[tid] = g_pools[p0 * SEG + within + tid];
    sa1[tid] = g_pools[p1 * SEG + within + tid];
    sa2[tid] = g_pools[p2 * SEG + within + tid];
    __syncthreads();

    const int n = tid * 4;
    const float* wp = Wf + (size_t)k0 * NOUT + n;

    float4 s0 = make_float4(0.f, 0.f, 0.f, 0.f);
    float4 s1 = s0, s2 = s0;

    for (int d = 0; d < KCHUNK; d += 8) {
        float4 w[8];
        #pragma unroll
        for (int u = 0; u < 8; u++)
            w[u] = __ldcs((const float4*)(wp + (size_t)u * NOUT));
        wp += 8 * NOUT;
        #pragma unroll
        for (int u = 0; u < 8; u++) {
            float x0 = sa0[d + u];
            float x1 = sa1[d + u];
            float x2 = sa2[d + u];
            s0.x = fmaf(x0, w[u].x, s0.x); s0.y = fmaf(x0, w[u].y, s0.y);
            s0.z = fmaf(x0, w[u].z, s0.z); s0.w = fmaf(x0, w[u].w, s0.w);
            s1.x = fmaf(x1, w[u].x, s1.x); s1.y = fmaf(x1, w[u].y, s1.y);
            s1.z = fmaf(x1, w[u].z, s1.z); s1.w = fmaf(x1, w[u].w, s1.w);
            s2.x = fmaf(x2, w[u].x, s2.x); s2.y = fmaf(x2, w[u].y, s2.y);
            s2.z = fmaf(x2, w[u].z, s2.z); s2.w = fmaf(x2, w[u].w, s2.w);
        }
    }

    float* outp = g_partial + (size_t)chunk * 3 * NOUT;
    *(float4*)(outp + n)            = s0;
    *(float4*)(outp + NOUT + n)     = s1;
    *(float4*)(outp + 2 * NOUT + n) = s2;
}

// ---------------------------------------------------------------------------
// Deterministic reduce + bias. 96 blocks x 1024 threads.
// Block covers 32 outputs (lane, coalesced) x 32 K-part slices (<=19 chunks
// each), then SMEM tree over parts.
// ---------------------------------------------------------------------------
__global__ void __launch_bounds__(1024) reduce_kernel(
    const float* __restrict__ bias, float* __restrict__ out)
{
    __shared__ float red[RPARTS * 32];
    const int tid  = threadIdx.x;
    const int lane = tid & 31;
    const int part = tid >> 5;                       // 0..31
    const int i    = blockIdx.x * 32 + lane;         // output index 0..3071

    const int cbeg = part * RCPP;
    const int cend = min(NCHUNKS, cbeg + RCPP);

    float s = 0.f;
    const float* src = g_partial + (size_t)cbeg * (3 * NOUT) + i;
    #pragma unroll
    for (int k = 0; k < RCPP; k++) {
        if (cbeg + k < cend)
            s += src[(size_t)k * (3 * NOUT)];
    }

    red[part * 32 + lane] = s;
    __syncthreads();

    #pragma unroll
    for (int st = RPARTS / 2; st > 0; st >>= 1) {
        if (part < st)
            red[part * 32 + lane] += red[(part + st) * 32 + lane];
        __syncthreads();
    }

    if (part == 0)
        out[i] = red[lane] + bias[i & (NOUT - 1)];
}

extern "C" void kernel_launch(void* const* d_in, const int* in_sizes, int n_in,
                              void* d_out, int out_size)
{
    const float* feature = (const float*)d_in[0];
    const float* pbox    = (const float*)d_in[1];
    const float* obox    = (const float*)d_in[2];
    const float* ratio   = (const float*)d_in[3];
    const float* Wf      = (const float*)d_in[4];
    const float* bias    = (const float*)d_in[5];
    float* out = (float*)d_out;

    prefetch_kernel<<<PF_BLKS, 256>>>(Wf);
    dim3 pgrid(CCH, 4);
    pool_kernel<<<pgrid, 256>>>(feature, pbox, obox, ratio);
    gemm_kernel<<<NCHUNKS, 256>>>(Wf);
    reduce_kernel<<<96, 1024>>>(bias, out);
}